// round 14
// baseline (speedup 1.0000x reference)
#include <cuda_runtime.h>
#include <cstdint>

// FeatureResidual: 1-NN over 8-dim keys in a 100000x40 table, then feature residual.
#define BATCH  1024
#define KDIM   8
#define FDIM   32
#define NROWS  100000
#define NCOLS  40

#define NSLICES   296               // grid = 296 blocks = 2/SM exact wave
#define TPB       128
#define QPT       8                 // queries per thread (128*8 = all 1024 per block)
#define ROWS_PER  338               // 296*338 >= 100000; last slice 290 (even)
#define MAXPAIRS  169
#define REC       20                // floats per pair record: 16 key + 2 nh + 2 pad

typedef unsigned long long u64;

// Per-query packed (enc(score) << 32 | ~row). Max = best score; ties -> lowest row.
// Zero-initialized at module load; finalize_kernel resets to 0 each launch.
__device__ u64 g_best[BATCH];

// ---------- f32x2 helpers ----------
__device__ __forceinline__ u64 pack2(float lo, float hi) {
    u64 r; asm("mov.b64 %0, {%1, %2};" : "=l"(r) : "f"(lo), "f"(hi)); return r;
}
__device__ __forceinline__ void unpack2(u64 p, float &lo, float &hi) {
    asm("mov.b64 {%0, %1}, %2;" : "=f"(lo), "=f"(hi) : "l"(p));
}
__device__ __forceinline__ u64 fma2(u64 a, u64 b, u64 c) {
    u64 d; asm("fma.rn.f32x2 %0, %1, %2, %3;" : "=l"(d) : "l"(a), "l"(b), "l"(c)); return d;
}
// Monotonic-increasing encode of float (u32 compare order == float order).
// Always > 0 for finite inputs, so g_best==0 is a safe atomicMax identity.
__device__ __forceinline__ unsigned enc_inc(float f) {
    int s = __float_as_int(f);
    return (s < 0) ? ~(unsigned)s : ((unsigned)s | 0x80000000u);
}

__global__ __launch_bounds__(TPB, 2)   // 255-reg budget: q[8][8] (128) + record (18) + misc
void argmin_kernel(const float* __restrict__ pk,
                   const float* __restrict__ table,
                   const int*   __restrict__ kidx) {
    // Pair record p (80B, 16B-aligned): [k0e,k0o, ..., k7e,k7o, nh_e,nh_o, pad,pad]
    __shared__ __align__(16) float sRec[MAXPAIRS * REC];
    __shared__ int sKidx[KDIM];

    const int t     = threadIdx.x;
    const int slice = blockIdx.x;

    if (t < KDIM) sKidx[t] = kidx[t];
    __syncthreads();

    const int rowBase = slice * ROWS_PER;
    const int nr      = min(ROWS_PER, NROWS - rowBase);   // even for this geometry
    const int npairs  = nr >> 1;

    // Stage keys interleaved by row pair (float2 fast path when key cols contiguous).
    bool kcontig = ((sKidx[0] & 1) == 0);
    #pragma unroll
    for (int i = 1; i < KDIM; i++) kcontig = kcontig && (sKidx[i] == sKidx[0] + i);
    if (kcontig) {
        const int c0 = sKidx[0];
        for (int e = t; e < nr * (KDIM / 2); e += TPB) {
            int r = e >> 2, c2 = e & 3;
            float2 v = *(const float2*)(table + (size_t)(rowBase + r) * NCOLS + c0 + 2 * c2);
            float* dst = sRec + (r >> 1) * REC + (r & 1);
            dst[4 * c2]     = v.x;
            dst[4 * c2 + 2] = v.y;
        }
    } else {
        for (int e = t; e < nr * KDIM; e += TPB) {
            int r = e >> 3, c = e & 7;
            float v = table[(size_t)(rowBase + r) * NCOLS + sKidx[c]];
            sRec[(r >> 1) * REC + (c << 1) + (r & 1)] = v;
        }
    }
    __syncthreads();
    // -0.5*||k||^2 per row, stored pair-adjacent at record offset 16.
    for (int r = t; r < nr; r += TPB) {
        const float* kr = sRec + (r >> 1) * REC + (r & 1);
        float s = kr[0] * kr[0];
        #pragma unroll
        for (int i = 1; i < KDIM; i++) s = fmaf(kr[2 * i], kr[2 * i], s);
        sRec[(r >> 1) * REC + 16 + (r & 1)] = -0.5f * s;
    }

    // Prologue: 8 queries per thread, duplicate-packed (128 regs).
    u64 q[QPT][KDIM];
    #pragma unroll
    for (int j = 0; j < QPT; j++) {
        const float4* pq = (const float4*)(pk + (size_t)(t + TPB * j) * KDIM);
        float4 a0 = pq[0], a1 = pq[1];
        float a[KDIM] = {a0.x, a0.y, a0.z, a0.w, a1.x, a1.y, a1.z, a1.w};
        #pragma unroll
        for (int i = 0; i < KDIM; i++) q[j][i] = pack2(a[i], a[i]);
    }

    float bs[QPT];
    int   bp[QPT];
    #pragma unroll
    for (int j = 0; j < QPT; j++) { bs[j] = -__int_as_float(0x7f800000); bp[j] = 0; }

    __syncthreads();

    // Flat hot loop: 5 LDS (80B record, amortized over 8 queries = half the
    // crossbar bytes per score vs QPT=4) + 64 FFMA2 + 8 minimal updates.
    #pragma unroll 1
    for (int p = 0; p < npairs; p++) {
        const ulonglong2* R = (const ulonglong2*)(sRec + p * REC);
        ulonglong2 r0 = R[0], r1 = R[1], r2 = R[2], r3 = R[3];
        u64 nh2 = *(const u64*)(sRec + p * REC + 16);
        #pragma unroll
        for (int j = 0; j < QPT; j++) {
            // score = q.k - 0.5*||k||^2 for rows (2p, 2p+1) simultaneously
            u64 acc = fma2(q[j][0], r0.x, nh2);
            acc = fma2(q[j][1], r0.y, acc);
            acc = fma2(q[j][2], r1.x, acc);
            acc = fma2(q[j][3], r1.y, acc);
            acc = fma2(q[j][4], r2.x, acc);
            acc = fma2(q[j][5], r2.y, acc);
            acc = fma2(q[j][6], r3.x, acc);
            acc = fma2(q[j][7], r3.y, acc);
            float s0, s1; unpack2(acc, s0, s1);
            float m = fmaxf(s0, s1);
            bool g = m > bs[j];                 // strict: earliest pair wins ties
            bp[j] = g ? p : bp[j];
            bs[j] = fmaxf(m, bs[j]);
        }
    }

    // Resolve in-pair index for winning pair (bit-identical re-score), then atomicMax.
    #pragma unroll
    for (int j = 0; j < QPT; j++) {
        const ulonglong2* R = (const ulonglong2*)(sRec + bp[j] * REC);
        ulonglong2 r0 = R[0], r1 = R[1], r2 = R[2], r3 = R[3];
        u64 nh2 = *(const u64*)(sRec + bp[j] * REC + 16);
        u64 acc = fma2(q[j][0], r0.x, nh2);
        acc = fma2(q[j][1], r0.y, acc);
        acc = fma2(q[j][2], r1.x, acc);
        acc = fma2(q[j][3], r1.y, acc);
        acc = fma2(q[j][4], r2.x, acc);
        acc = fma2(q[j][5], r2.y, acc);
        acc = fma2(q[j][6], r3.x, acc);
        acc = fma2(q[j][7], r3.y, acc);
        float s0, s1; unpack2(acc, s0, s1);
        int row = rowBase + 2 * bp[j] + (s1 > s0 ? 1 : 0);  // even row wins in-pair ties
        int qidx = t + TPB * j;
        u64 key = ((u64)enc_inc(bs[j]) << 32) | (unsigned)(~(unsigned)row);
        atomicMax(&g_best[qidx], key);
    }
}

// One warp per query: lane0 reads winner, broadcasts, lanes compute residual,
// lane0 resets g_best for the next graph replay (deterministic).
__global__ void finalize_kernel(const float* __restrict__ feat,
                                const float* __restrict__ table,
                                const int*   __restrict__ fidx,
                                float* __restrict__ out) {
    int warp = (blockIdx.x * blockDim.x + threadIdx.x) >> 5;
    int lane = threadIdx.x & 31;
    if (warp >= BATCH) return;
    u64 v = 0;
    if (lane == 0) v = g_best[warp];
    v = __shfl_sync(0xFFFFFFFFu, v, 0);
    int row = (int)(~(unsigned)v);
    int col = fidx[lane];
    out[warp * FDIM + lane] = feat[warp * FDIM + lane]
                            - table[(size_t)row * NCOLS + col];
    if (lane == 0) g_best[warp] = 0ULL;
}

extern "C" void kernel_launch(void* const* d_in, const int* in_sizes, int n_in,
                              void* d_out, int out_size) {
    const float* pk    = (const float*)d_in[0];  // predicted_key [1024,8]
    const float* feat  = (const float*)d_in[1];  // features      [1024,32]
    const float* table = (const float*)d_in[2];  // lookup_table  [100000,40]
    const int*   kidx  = (const int*)  d_in[3];  // lookup_key_indices [8]
    const int*   fidx  = (const int*)  d_in[4];  // feature_indices    [32]
    float* out = (float*)d_out;

    argmin_kernel<<<NSLICES, TPB>>>(pk, table, kidx);
    finalize_kernel<<<(BATCH * 32 + 255) / 256, 256>>>(feat, table, fidx, out);
}

// round 15
// speedup vs baseline: 1.0901x; 1.0901x over previous
#include <cuda_runtime.h>
#include <cstdint>

// FeatureResidual: 1-NN over 8-dim keys in a 100000x40 table, then feature residual.
#define BATCH  1024
#define KDIM   8
#define FDIM   32
#define NROWS  100000
#define NCOLS  40

#define QGROUPS   2                 // query halves (512 queries each)
#define NSLICES   296               // grid = 296 x 2 = 592 blocks = 4/SM exact wave
#define TPB       128
#define QPT       4                 // queries per thread (128*4 = 512 per block)
#define ROWS_PER  338               // 296*338 >= 100000; last slice 290 (even)
#define MAXPAIRS  169
#define REC       20                // floats per pair record: 16 key + 2 nh + 2 pad

typedef unsigned long long u64;

// Per-query packed (enc(score) << 32 | ~row). Max = best score; ties -> lowest row.
// Zero-initialized at module load; finalize_kernel resets to 0 each launch.
__device__ u64 g_best[BATCH];

// ---------- f32x2 helpers ----------
__device__ __forceinline__ u64 pack2(float lo, float hi) {
    u64 r; asm("mov.b64 %0, {%1, %2};" : "=l"(r) : "f"(lo), "f"(hi)); return r;
}
__device__ __forceinline__ void unpack2(u64 p, float &lo, float &hi) {
    asm("mov.b64 {%0, %1}, %2;" : "=f"(lo), "=f"(hi) : "l"(p));
}
__device__ __forceinline__ u64 fma2(u64 a, u64 b, u64 c) {
    u64 d; asm("fma.rn.f32x2 %0, %1, %2, %3;" : "=l"(d) : "l"(a), "l"(b), "l"(c)); return d;
}
// Monotonic-increasing encode of float (u32 compare order == float order).
// Always > 0 for finite inputs, so g_best==0 is a safe atomicMax identity.
__device__ __forceinline__ unsigned enc_inc(float f) {
    int s = __float_as_int(f);
    return (s < 0) ? ~(unsigned)s : ((unsigned)s | 0x80000000u);
}

// Score all QPT queries against one pair record, DIM-MAJOR: consecutive FFMA2s
// share the key operand k_i -> HW operand-reuse cache -> RF-bank rt 2 (not 3).
// acc[j] chains stay independent (dep distance = QPT instructions).
#define SCORE_DIM_MAJOR(r0, r1, r2, r3, nh2, a)                           \
    do {                                                                  \
        (a)[0] = fma2(q[0][0], (r0).x, (nh2));                            \
        (a)[1] = fma2(q[1][0], (r0).x, (nh2));                            \
        (a)[2] = fma2(q[2][0], (r0).x, (nh2));                            \
        (a)[3] = fma2(q[3][0], (r0).x, (nh2));                            \
        (a)[0] = fma2(q[0][1], (r0).y, (a)[0]);                           \
        (a)[1] = fma2(q[1][1], (r0).y, (a)[1]);                           \
        (a)[2] = fma2(q[2][1], (r0).y, (a)[2]);                           \
        (a)[3] = fma2(q[3][1], (r0).y, (a)[3]);                           \
        (a)[0] = fma2(q[0][2], (r1).x, (a)[0]);                           \
        (a)[1] = fma2(q[1][2], (r1).x, (a)[1]);                           \
        (a)[2] = fma2(q[2][2], (r1).x, (a)[2]);                           \
        (a)[3] = fma2(q[3][2], (r1).x, (a)[3]);                           \
        (a)[0] = fma2(q[0][3], (r1).y, (a)[0]);                           \
        (a)[1] = fma2(q[1][3], (r1).y, (a)[1]);                           \
        (a)[2] = fma2(q[2][3], (r1).y, (a)[2]);                           \
        (a)[3] = fma2(q[3][3], (r1).y, (a)[3]);                           \
        (a)[0] = fma2(q[0][4], (r2).x, (a)[0]);                           \
        (a)[1] = fma2(q[1][4], (r2).x, (a)[1]);                           \
        (a)[2] = fma2(q[2][4], (r2).x, (a)[2]);                           \
        (a)[3] = fma2(q[3][4], (r2).x, (a)[3]);                           \
        (a)[0] = fma2(q[0][5], (r2).y, (a)[0]);                           \
        (a)[1] = fma2(q[1][5], (r2).y, (a)[1]);                           \
        (a)[2] = fma2(q[2][5], (r2).y, (a)[2]);                           \
        (a)[3] = fma2(q[3][5], (r2).y, (a)[3]);                           \
        (a)[0] = fma2(q[0][6], (r3).x, (a)[0]);                           \
        (a)[1] = fma2(q[1][6], (r3).x, (a)[1]);                           \
        (a)[2] = fma2(q[2][6], (r3).x, (a)[2]);                           \
        (a)[3] = fma2(q[3][6], (r3).x, (a)[3]);                           \
        (a)[0] = fma2(q[0][7], (r3).y, (a)[0]);                           \
        (a)[1] = fma2(q[1][7], (r3).y, (a)[1]);                           \
        (a)[2] = fma2(q[2][7], (r3).y, (a)[2]);                           \
        (a)[3] = fma2(q[3][7], (r3).y, (a)[3]);                           \
    } while (0)

__global__ __launch_bounds__(TPB, 4)   // unfused: hot-loop liveness only
void argmin_kernel(const float* __restrict__ pk,
                   const float* __restrict__ table,
                   const int*   __restrict__ kidx) {
    // Pair record p (80B, 16B-aligned): [k0e,k0o, ..., k7e,k7o, nh_e,nh_o, pad,pad]
    __shared__ __align__(16) float sRec[MAXPAIRS * REC];
    __shared__ int sKidx[KDIM];

    const int t     = threadIdx.x;
    const int slice = blockIdx.x;
    const int grp   = blockIdx.y;

    if (t < KDIM) sKidx[t] = kidx[t];
    __syncthreads();

    const int rowBase = slice * ROWS_PER;
    const int nr      = min(ROWS_PER, NROWS - rowBase);   // even for this geometry
    const int npairs  = nr >> 1;

    // Stage keys interleaved by row pair (float2 fast path when key cols contiguous).
    bool kcontig = ((sKidx[0] & 1) == 0);
    #pragma unroll
    for (int i = 1; i < KDIM; i++) kcontig = kcontig && (sKidx[i] == sKidx[0] + i);
    if (kcontig) {
        const int c0 = sKidx[0];
        for (int e = t; e < nr * (KDIM / 2); e += TPB) {
            int r = e >> 2, c2 = e & 3;
            float2 v = *(const float2*)(table + (size_t)(rowBase + r) * NCOLS + c0 + 2 * c2);
            float* dst = sRec + (r >> 1) * REC + (r & 1);
            dst[4 * c2]     = v.x;
            dst[4 * c2 + 2] = v.y;
        }
    } else {
        for (int e = t; e < nr * KDIM; e += TPB) {
            int r = e >> 3, c = e & 7;
            float v = table[(size_t)(rowBase + r) * NCOLS + sKidx[c]];
            sRec[(r >> 1) * REC + (c << 1) + (r & 1)] = v;
        }
    }
    __syncthreads();
    // -0.5*||k||^2 per row, stored pair-adjacent at record offset 16.
    for (int r = t; r < nr; r += TPB) {
        const float* kr = sRec + (r >> 1) * REC + (r & 1);
        float s = kr[0] * kr[0];
        #pragma unroll
        for (int i = 1; i < KDIM; i++) s = fmaf(kr[2 * i], kr[2 * i], s);
        sRec[(r >> 1) * REC + 16 + (r & 1)] = -0.5f * s;
    }

    // Prologue: 4 queries per thread, duplicate-packed (64 regs).
    const int qbase = grp * (TPB * QPT);
    u64 q[QPT][KDIM];
    #pragma unroll
    for (int j = 0; j < QPT; j++) {
        const float4* pq = (const float4*)(pk + (size_t)(qbase + t + TPB * j) * KDIM);
        float4 a0 = pq[0], a1 = pq[1];
        float a[KDIM] = {a0.x, a0.y, a0.z, a0.w, a1.x, a1.y, a1.z, a1.w};
        #pragma unroll
        for (int i = 0; i < KDIM; i++) q[j][i] = pack2(a[i], a[i]);
    }

    float bs[QPT];
    int   bp[QPT];
    #pragma unroll
    for (int j = 0; j < QPT; j++) { bs[j] = -__int_as_float(0x7f800000); bp[j] = 0; }

    __syncthreads();

    // Flat hot loop (R11 geometry), dim-major FFMA2 order for operand reuse.
    #pragma unroll 1
    for (int p = 0; p < npairs; p++) {
        const ulonglong2* R = (const ulonglong2*)(sRec + p * REC);
        ulonglong2 r0 = R[0], r1 = R[1], r2 = R[2], r3 = R[3];
        u64 nh2 = *(const u64*)(sRec + p * REC + 16);
        u64 a[QPT];
        SCORE_DIM_MAJOR(r0, r1, r2, r3, nh2, a);
        #pragma unroll
        for (int j = 0; j < QPT; j++) {
            float s0, s1; unpack2(a[j], s0, s1);
            float m = fmaxf(s0, s1);
            bool g = m > bs[j];                 // strict: earliest pair wins ties
            bp[j] = g ? p : bp[j];
            bs[j] = fmaxf(m, bs[j]);
        }
    }

    // Resolve in-pair index for winning pair (bit-identical re-score), then atomicMax.
    #pragma unroll
    for (int j = 0; j < QPT; j++) {
        const ulonglong2* R = (const ulonglong2*)(sRec + bp[j] * REC);
        ulonglong2 r0 = R[0], r1 = R[1], r2 = R[2], r3 = R[3];
        u64 nh2 = *(const u64*)(sRec + bp[j] * REC + 16);
        u64 acc = fma2(q[j][0], r0.x, nh2);
        acc = fma2(q[j][1], r0.y, acc);
        acc = fma2(q[j][2], r1.x, acc);
        acc = fma2(q[j][3], r1.y, acc);
        acc = fma2(q[j][4], r2.x, acc);
        acc = fma2(q[j][5], r2.y, acc);
        acc = fma2(q[j][6], r3.x, acc);
        acc = fma2(q[j][7], r3.y, acc);
        float s0, s1; unpack2(acc, s0, s1);
        int row = rowBase + 2 * bp[j] + (s1 > s0 ? 1 : 0);  // even row wins in-pair ties
        int qidx = qbase + t + TPB * j;
        u64 key = ((u64)enc_inc(bs[j]) << 32) | (unsigned)(~(unsigned)row);
        atomicMax(&g_best[qidx], key);
    }
}

// One warp per query: lane0 reads winner, broadcasts, lanes compute residual,
// lane0 resets g_best for the next graph replay (deterministic).
__global__ void finalize_kernel(const float* __restrict__ feat,
                                const float* __restrict__ table,
                                const int*   __restrict__ fidx,
                                float* __restrict__ out) {
    int warp = (blockIdx.x * blockDim.x + threadIdx.x) >> 5;
    int lane = threadIdx.x & 31;
    if (warp >= BATCH) return;
    u64 v = 0;
    if (lane == 0) v = g_best[warp];
    v = __shfl_sync(0xFFFFFFFFu, v, 0);
    int row = (int)(~(unsigned)v);
    int col = fidx[lane];
    out[warp * FDIM + lane] = feat[warp * FDIM + lane]
                            - table[(size_t)row * NCOLS + col];
    if (lane == 0) g_best[warp] = 0ULL;
}

extern "C" void kernel_launch(void* const* d_in, const int* in_sizes, int n_in,
                              void* d_out, int out_size) {
    const float* pk    = (const float*)d_in[0];  // predicted_key [1024,8]
    const float* feat  = (const float*)d_in[1];  // features      [1024,32]
    const float* table = (const float*)d_in[2];  // lookup_table  [100000,40]
    const int*   kidx  = (const int*)  d_in[3];  // lookup_key_indices [8]
    const int*   fidx  = (const int*)  d_in[4];  // feature_indices    [32]
    float* out = (float*)d_out;

    dim3 grid(NSLICES, QGROUPS);
    argmin_kernel<<<grid, TPB>>>(pk, table, kidx);
    finalize_kernel<<<(BATCH * 32 + 255) / 256, 256>>>(feat, table, fidx, out);
}